// round 14
// baseline (speedup 1.0000x reference)
#include <cuda_runtime.h>
#include <math.h>

// ---------------------------------------------------------------------------
// Problem constants
// ---------------------------------------------------------------------------
constexpr int Hdim = 512;              // hidden
constexpr int Bdim = 2048;             // E*S
constexpr int Ldim = 20;               // comm steps
constexpr int Cdim = 32;               // comm shape
constexpr int OUT_CO = Bdim * Ldim * Cdim;

// ---------------------------------------------------------------------------
// Scratch (device globals -- no allocation allowed)
// ---------------------------------------------------------------------------
__device__ float g_ax[Bdim * Hdim];
__device__ float g_az[Bdim * Hdim];
__device__ float g_an[Bdim * Hdim];
__device__ float g_z [Bdim * Hdim];
__device__ float g_rh[Bdim * Hdim];
__device__ float g_hsT[Bdim * Ldim * Hdim];   // (B, L, H) hidden states
__device__ float g_y  [Bdim * Ldim * Hdim];   // conv output (B, L, 512)
__device__ float g_convB[16 * Hdim * 128];    // repacked conv weights, slot-major
__device__ float g_Bcomb[Hdim * 64];          // [W_mu | W_std]
__device__ float g_p[Bdim * Ldim * 64];

// ---------------------------------------------------------------------------
// Helpers
// ---------------------------------------------------------------------------
__device__ __forceinline__ float sigm(float x) { return 1.0f / (1.0f + expf(-x)); }

typedef unsigned long long ull;

__device__ __forceinline__ ull f32x2_dup(float a) {
    ull r; asm("mov.b64 %0, {%1, %1};" : "=l"(r) : "f"(a)); return r;
}
__device__ __forceinline__ ull fma2(ull a, ull b, ull c) {
    ull d; asm("fma.rn.f32x2 %0, %1, %2, %3;" : "=l"(d) : "l"(a), "l"(b), "l"(c));
    return d;
}
__device__ __forceinline__ void f32x2_unpack(ull v, float& lo, float& hi) {
    asm("mov.b64 {%0, %1}, %2;" : "=f"(lo), "=f"(hi) : "l"(v));
}

// ===========================================================================
// Core 1 (BK=32, templated BM): BM x 64 tile, 256 threads.
// Thread tile (BM/16 rows = BM/32 pairs) x 4 cols.
// A chunk map: idx = tid*(BM/32)+i -> row = idx>>3, kq = (idx&7)*4.
// B chunk map: i in {0,1} -> kr = (tid>>4)+16*i, nq = (tid&15)*4.
// ===========================================================================
template<int BM>
__device__ __forceinline__ void gemm_compute1(ull (&acc)[BM/32][4],
                                              const float (&As)[32][BM],
                                              const float (&Bs)[32][64],
                                              int ty, int tx) {
    constexpr int P = BM / 32;
#pragma unroll
    for (int kk = 0; kk < 32; kk++) {
        ull a[P];
#pragma unroll
        for (int q = 0; q < P / 2; q++) {
            ulonglong2 t2 = *(const ulonglong2*)&As[kk][ty * (2 * P) + 4 * q];
            a[2 * q] = t2.x; a[2 * q + 1] = t2.y;
        }
        float4 b = *(const float4*)&Bs[kk][tx * 4];
        ull bd[4] = {f32x2_dup(b.x), f32x2_dup(b.y), f32x2_dup(b.z), f32x2_dup(b.w)};
#pragma unroll
        for (int p = 0; p < P; p++)
#pragma unroll
            for (int c = 0; c < 4; c++)
                acc[p][c] = fma2(a[p], bd[c], acc[p][c]);
    }
}

template<int BM>
__device__ __forceinline__ void store_frag1(float (&As)[32][BM], float (&Bs)[32][64],
                                            const float4* ar, const float4* br, int tid) {
    constexpr int A4 = BM / 32;
#pragma unroll
    for (int i = 0; i < A4; i++) {
        int idx = tid * A4 + i;
        int row = idx >> 3, kq = (idx & 7) * 4;
        As[kq + 0][row] = ar[i].x; As[kq + 1][row] = ar[i].y;
        As[kq + 2][row] = ar[i].z; As[kq + 3][row] = ar[i].w;
    }
    int kr = tid >> 4, nq = (tid & 15) * 4;
    *(float4*)&Bs[kr][nq]      = br[0];
    *(float4*)&Bs[kr + 16][nq] = br[1];
}

// loadA(k0, idx): idx = tid*(BM/32)+i; row = idx>>3; kq = (idx&7)*4
template<int BM, typename LA>
__device__ __forceinline__ void run_gemm1(ull (&acc)[BM/32][4], LA loadA,
                                          const float* __restrict__ Bsrc, int ldb,
                                          int bn0, int K,
                                          float (&As)[2][32][BM],
                                          float (&Bs)[2][32][64], int tid) {
    constexpr int A4 = BM / 32;
    const int ty = tid >> 4, tx = tid & 15;
    const int kr = tid >> 4, nq = (tid & 15) * 4;
    float4 ar[A4], br[2];
#pragma unroll
    for (int i = 0; i < A4; i++) ar[i] = loadA(0, tid * A4 + i);
#pragma unroll
    for (int i = 0; i < 2; i++)
        br[i] = *(const float4*)(Bsrc + (size_t)(kr + 16 * i) * ldb + bn0 + nq);
    store_frag1<BM>(As[0], Bs[0], ar, br, tid);
    __syncthreads();
    int buf = 0;
    for (int k0 = 32; k0 < K; k0 += 32) {
#pragma unroll
        for (int i = 0; i < A4; i++) ar[i] = loadA(k0, tid * A4 + i);
#pragma unroll
        for (int i = 0; i < 2; i++)
            br[i] = *(const float4*)(Bsrc + (size_t)(k0 + kr + 16 * i) * ldb + bn0 + nq);
        gemm_compute1<BM>(acc, As[buf], Bs[buf], ty, tx);
        store_frag1<BM>(As[buf ^ 1], Bs[buf ^ 1], ar, br, tid);
        buf ^= 1;
        __syncthreads();
    }
    gemm_compute1<BM>(acc, As[buf], Bs[buf], ty, tx);
}

// ===========================================================================
// Core 2 (BK=16): 128 x 128 tile, 256 threads, thread tile 8x8 (conv).
// ===========================================================================
__device__ __forceinline__ void gemm_compute8(ull (&acc)[4][8],
                                              const float (&As)[16][128],
                                              const float (&Bs)[16][128],
                                              int ty, int tx) {
#pragma unroll
    for (int kk = 0; kk < 16; kk++) {
        ulonglong2 a01 = *(const ulonglong2*)&As[kk][ty * 8];
        ulonglong2 a23 = *(const ulonglong2*)&As[kk][ty * 8 + 4];
        ull a[4] = {a01.x, a01.y, a23.x, a23.y};
        {
            float4 b0 = *(const float4*)&Bs[kk][tx * 4];
            ull bd[4] = {f32x2_dup(b0.x), f32x2_dup(b0.y),
                         f32x2_dup(b0.z), f32x2_dup(b0.w)};
#pragma unroll
            for (int p = 0; p < 4; p++)
#pragma unroll
                for (int c = 0; c < 4; c++)
                    acc[p][c] = fma2(a[p], bd[c], acc[p][c]);
        }
        {
            float4 b1 = *(const float4*)&Bs[kk][64 + tx * 4];
            ull bd[4] = {f32x2_dup(b1.x), f32x2_dup(b1.y),
                         f32x2_dup(b1.z), f32x2_dup(b1.w)};
#pragma unroll
            for (int p = 0; p < 4; p++)
#pragma unroll
                for (int c = 0; c < 4; c++)
                    acc[p][4 + c] = fma2(a[p], bd[c], acc[p][4 + c]);
        }
    }
}

__device__ __forceinline__ void store_frag8(float (&As)[16][128], float (&Bs)[16][128],
                                            const float4* ar, const float4* br, int tid) {
#pragma unroll
    for (int i = 0; i < 2; i++) {
        int idx = tid * 2 + i;
        int row = idx >> 2, kq = (idx & 3) * 4;
        As[kq + 0][row] = ar[i].x; As[kq + 1][row] = ar[i].y;
        As[kq + 2][row] = ar[i].z; As[kq + 3][row] = ar[i].w;
    }
    int kr = tid >> 4, nq = (tid & 15) * 8;
    *(float4*)&Bs[kr][nq]     = br[0];
    *(float4*)&Bs[kr][nq + 4] = br[1];
}

template<typename LA>
__device__ __forceinline__ void run_gemm8(ull (&acc)[4][8], LA loadA,
                                          const float* __restrict__ Bsrc, int ldb,
                                          int bn0, int K,
                                          float (&As)[2][16][128],
                                          float (&Bs)[2][16][128], int tid) {
    const int ty = tid >> 4, tx = tid & 15;
    const int kr = tid >> 4, nq = (tid & 15) * 8;
    float4 ar[2], br[2];
#pragma unroll
    for (int i = 0; i < 2; i++) ar[i] = loadA(0, tid * 2 + i);
    br[0] = *(const float4*)(Bsrc + (size_t)kr * ldb + bn0 + nq);
    br[1] = *(const float4*)(Bsrc + (size_t)kr * ldb + bn0 + nq + 4);
    store_frag8(As[0], Bs[0], ar, br, tid);
    __syncthreads();
    int buf = 0;
    for (int k0 = 16; k0 < K; k0 += 16) {
#pragma unroll
        for (int i = 0; i < 2; i++) ar[i] = loadA(k0, tid * 2 + i);
        br[0] = *(const float4*)(Bsrc + (size_t)(k0 + kr) * ldb + bn0 + nq);
        br[1] = *(const float4*)(Bsrc + (size_t)(k0 + kr) * ldb + bn0 + nq + 4);
        gemm_compute8(acc, As[buf], Bs[buf], ty, tx);
        store_frag8(As[buf ^ 1], Bs[buf ^ 1], ar, br, tid);
        buf ^= 1;
        __syncthreads();
    }
    gemm_compute8(acc, As[buf], Bs[buf], ty, tx);
}

// ---------------------------------------------------------------------------
// Weight repack: conv weights -> slot-major (slot, c, o); [W_mu | W_std] pack
// ---------------------------------------------------------------------------
__global__ void k_pack(const float* __restrict__ w1, const float* __restrict__ w3,
                       const float* __restrict__ w5, const float* __restrict__ w7,
                       const float* __restrict__ Wmu, const float* __restrict__ Wstd) {
    const int totalConv = 16 * Hdim * 128;
    const int totalComb = Hdim * 64;
    for (int idx = blockIdx.x * blockDim.x + threadIdx.x;
         idx < totalConv + totalComb; idx += gridDim.x * blockDim.x) {
        if (idx < totalConv) {
            int slot = idx >> 16;
            int rem  = idx & 65535;
            int c    = rem >> 7;
            int o    = rem & 127;
            const float* w; int kg, j;
            if (slot == 0)      { w = w1; kg = 1; j = 0; }
            else if (slot < 4)  { w = w3; kg = 3; j = slot - 1; }
            else if (slot < 9)  { w = w5; kg = 5; j = slot - 4; }
            else                { w = w7; kg = 7; j = slot - 9; }
            g_convB[idx] = w[(size_t)o * Hdim * kg + c * kg + j];
        } else {
            int i2 = idx - totalConv;
            int k = i2 >> 6;
            int n = i2 & 63;
            g_Bcomb[i2] = (n < 32) ? Wmu[k * 32 + n] : Wstd[k * 32 + (n - 32)];
        }
    }
}

// ---------------------------------------------------------------------------
// Precompute ax/az/an = xf @ W*[:H] + b*   (M=2048, N=1536, K=512)
// ---------------------------------------------------------------------------
__global__ __launch_bounds__(256) void k_pre(const float* __restrict__ x,
        const float* __restrict__ Wr, const float* __restrict__ br,
        const float* __restrict__ Wz, const float* __restrict__ bz,
        const float* __restrict__ Wn, const float* __restrict__ bnn) {
    __shared__ __align__(16) float As[2][32][128];
    __shared__ __align__(16) float Bs[2][32][64];
    const int tid = threadIdx.x, ty = tid >> 4, tx = tid & 15;
    const int bm = blockIdx.y * 128;
    const int bncol = blockIdx.x * 64;
    const int sel = bncol >> 9;
    const int nloc = bncol & 511;
    const float* W    = sel == 0 ? Wr : (sel == 1 ? Wz : Wn);
    const float* bias = sel == 0 ? br : (sel == 1 ? bz : bnn);
    float* out        = sel == 0 ? g_ax : (sel == 1 ? g_az : g_an);
    ull acc[4][4] = {};
    auto loadA = [&](int k0, int idx) -> float4 {
        int row = idx >> 3, kq = (idx & 7) * 4;
        return *(const float4*)(x + (size_t)(bm + row) * Hdim + k0 + kq);
    };
    run_gemm1<128>(acc, loadA, W, Hdim, nloc, Hdim, As, Bs, tid);
    const int n = nloc + tx * 4;
    float4 bv = *(const float4*)(bias + n);
#pragma unroll
    for (int p = 0; p < 4; p++) {
        float lo[4], hi[4];
#pragma unroll
        for (int c = 0; c < 4; c++) f32x2_unpack(acc[p][c], lo[c], hi[c]);
        int m0 = bm + ty * 8 + 2 * p;
        *(float4*)(out + (size_t)m0 * Hdim + n) =
            make_float4(lo[0] + bv.x, lo[1] + bv.y, lo[2] + bv.z, lo[3] + bv.w);
        *(float4*)(out + (size_t)(m0 + 1) * Hdim + n) =
            make_float4(hi[0] + bv.x, hi[1] + bv.y, hi[2] + bv.z, hi[3] + bv.w);
    }
}

// ---------------------------------------------------------------------------
// Step 0 (h=0): h1 = (1 - sigmoid(az)) * tanh(an)  ->  hsT[:, 0, :]
// ---------------------------------------------------------------------------
__global__ void k_step0() {
    for (int i = blockIdx.x * blockDim.x + threadIdx.x; i < Bdim * Hdim;
         i += gridDim.x * blockDim.x) {
        float z = sigm(g_az[i]);
        float hn = (1.0f - z) * tanhf(g_an[i]);
        int m = i >> 9, n = i & 511;
        g_hsT[(size_t)m * (Ldim * Hdim) + n] = hn;
    }
}

// ---------------------------------------------------------------------------
// Recurrence: r/z GEMM  (M=2048, N=1024 [r|z], K=512), 128x64, 256 CTAs
// ---------------------------------------------------------------------------
__global__ __launch_bounds__(256) void k_rz(const float* __restrict__ Wr,
                                            const float* __restrict__ Wz, int tm1) {
    __shared__ __align__(16) float As[2][32][128];
    __shared__ __align__(16) float Bs[2][32][64];
    const int tid = threadIdx.x, ty = tid >> 4, tx = tid & 15;
    const int bm = blockIdx.y * 128;
    const int bncol = blockIdx.x * 64;
    const int sel = bncol >> 9;              // 0 -> r, 1 -> z
    const int nloc = bncol & 511;
    const float* W = (sel == 0 ? Wr : Wz) + (size_t)Hdim * Hdim;
    const float* Ab = g_hsT + (size_t)tm1 * Hdim;
    ull acc[4][4] = {};
    auto loadA = [&](int k0, int idx) -> float4 {
        int row = idx >> 3, kq = (idx & 7) * 4;
        return *(const float4*)(Ab + (size_t)(bm + row) * (Ldim * Hdim) + k0 + kq);
    };
    run_gemm1<128>(acc, loadA, W, Hdim, nloc, Hdim, As, Bs, tid);
    const int n = nloc + tx * 4;
#pragma unroll
    for (int p = 0; p < 4; p++) {
        float lo[4], hi[4];
#pragma unroll
        for (int c = 0; c < 4; c++) f32x2_unpack(acc[p][c], lo[c], hi[c]);
        int m0 = bm + ty * 8 + 2 * p;
#pragma unroll
        for (int s = 0; s < 2; s++) {
            int m = m0 + s;
            float a0 = s ? hi[0] : lo[0], a1 = s ? hi[1] : lo[1];
            float a2 = s ? hi[2] : lo[2], a3 = s ? hi[3] : lo[3];
            size_t base = (size_t)m * Hdim + n;
            if (sel == 0) {
                float4 ax = *(const float4*)(g_ax + base);
                float4 hv = *(const float4*)(g_hsT + ((size_t)m * Ldim + tm1) * Hdim + n);
                *(float4*)(g_rh + base) = make_float4(
                    sigm(ax.x + a0) * hv.x, sigm(ax.y + a1) * hv.y,
                    sigm(ax.z + a2) * hv.z, sigm(ax.w + a3) * hv.w);
            } else {
                float4 az = *(const float4*)(g_az + base);
                *(float4*)(g_z + base) = make_float4(
                    sigm(az.x + a0), sigm(az.y + a1), sigm(az.z + a2), sigm(az.w + a3));
            }
        }
    }
}

// ---------------------------------------------------------------------------
// Recurrence: n GEMM + state update  (M=2048, N=512, K=512), 64x64, 256 CTAs
// ---------------------------------------------------------------------------
__global__ __launch_bounds__(256) void k_n(const float* __restrict__ Wn, int t) {
    __shared__ __align__(16) float As[2][32][64];
    __shared__ __align__(16) float Bs[2][32][64];
    const int tid = threadIdx.x, ty = tid >> 4, tx = tid & 15;
    const int bm = blockIdx.y * 64;
    const int bncol = blockIdx.x * 64;
    const int tm1 = t - 1;
    const float* W = Wn + (size_t)Hdim * Hdim;
    ull acc[2][4] = {};
    auto loadA = [&](int k0, int idx) -> float4 {
        int row = idx >> 3, kq = (idx & 7) * 4;
        return *(const float4*)(g_rh + (size_t)(bm + row) * Hdim + k0 + kq);
    };
    run_gemm1<64>(acc, loadA, W, Hdim, bncol, Hdim, As, Bs, tid);
    const int n = bncol + tx * 4;
#pragma unroll
    for (int p = 0; p < 2; p++) {
        float lo[4], hi[4];
#pragma unroll
        for (int c = 0; c < 4; c++) f32x2_unpack(acc[p][c], lo[c], hi[c]);
        int m0 = bm + ty * 4 + 2 * p;
#pragma unroll
        for (int s = 0; s < 2; s++) {
            int m = m0 + s;
            float a0 = s ? hi[0] : lo[0], a1 = s ? hi[1] : lo[1];
            float a2 = s ? hi[2] : lo[2], a3 = s ? hi[3] : lo[3];
            size_t base = (size_t)m * Hdim + n;
            float4 anv = *(const float4*)(g_an + base);
            float4 zv  = *(const float4*)(g_z + base);
            float4 hv  = *(const float4*)(g_hsT + ((size_t)m * Ldim + tm1) * Hdim + n);
            float nn0 = tanhf(anv.x + a0), nn1 = tanhf(anv.y + a1);
            float nn2 = tanhf(anv.z + a2), nn3 = tanhf(anv.w + a3);
            *(float4*)(g_hsT + ((size_t)m * Ldim + t) * Hdim + n) = make_float4(
                (1.0f - zv.x) * nn0 + zv.x * hv.x, (1.0f - zv.y) * nn1 + zv.y * hv.y,
                (1.0f - zv.z) * nn2 + zv.z * hv.z, (1.0f - zv.w) * nn3 + zv.w * hv.w);
        }
    }
}

// ---------------------------------------------------------------------------
// Multi-scale conv, groups interleaved on blockIdx.x for wave balance.
// 128(M) x 128(N = whole group) tiles, 8x8 thread tile. PReLU fused.
// ---------------------------------------------------------------------------
__global__ __launch_bounds__(256) void k_conv(const float* __restrict__ cb1,
                                              const float* __restrict__ cb3,
                                              const float* __restrict__ cb5,
                                              const float* __restrict__ cb7,
                                              const float* __restrict__ prelu_a) {
    __shared__ __align__(16) float As[2][16][128];
    __shared__ __align__(16) float Bs[2][16][128];
    const int tid = threadIdx.x, ty = tid >> 4, tx = tid & 15;
    const int g = blockIdx.x;          // interleaved: consecutive CTAs cycle groups
    const int taps = 2 * g + 1;
    const int pad  = g;
    const int slotBase[4] = {0, 1, 4, 9};
    const int colOff = g * 128;
    const float* bias = g == 0 ? cb1 : (g == 1 ? cb3 : (g == 2 ? cb5 : cb7));
    const int bm = blockIdx.y * 128;
    const float* Bsrc = g_convB + (size_t)slotBase[g] * 65536;
    const int K = taps * Hdim;
    int rowi[2], li[2];
#pragma unroll
    for (int i = 0; i < 2; i++) {
        int idx = tid * 2 + i;
        rowi[i] = bm + (idx >> 2);
        li[i] = rowi[i] % Ldim;
    }
    ull acc[4][8] = {};
    auto loadA = [&](int k0, int idx) -> float4 {
        int i = idx & 1;
        int kq = (idx & 3) * 4;
        int j = k0 >> 9;
        int dl = j - pad;
        int c = (k0 & 511) + kq;
        int lp = li[i] + dl;
        float4 v = make_float4(0.f, 0.f, 0.f, 0.f);
        if (lp >= 0 && lp < Ldim)
            v = *(const float4*)(g_hsT + (size_t)(rowi[i] + dl) * Hdim + c);
        return v;
    };
    run_gemm8(acc, loadA, Bsrc, 128, 0, K, As, Bs, tid);
    const float a = *prelu_a;
    const int n1 = tx * 4;
    const int n2 = 64 + tx * 4;
    float4 bv1 = *(const float4*)(bias + n1);
    float4 bv2 = *(const float4*)(bias + n2);
#pragma unroll
    for (int p = 0; p < 4; p++) {
        float lo[8], hi[8];
#pragma unroll
        for (int c = 0; c < 8; c++) f32x2_unpack(acc[p][c], lo[c], hi[c]);
        int m0 = bm + ty * 8 + 2 * p;
#pragma unroll
        for (int s = 0; s < 2; s++) {
            const float* v = s ? hi : lo;
            float* yrow = g_y + (size_t)(m0 + s) * Hdim + colOff;
            float u0 = v[0] + bv1.x, u1 = v[1] + bv1.y;
            float u2 = v[2] + bv1.z, u3 = v[3] + bv1.w;
            float u4 = v[4] + bv2.x, u5 = v[5] + bv2.y;
            float u6 = v[6] + bv2.z, u7 = v[7] + bv2.w;
            *(float4*)(yrow + n1) = make_float4(
                u0 >= 0.f ? u0 : a * u0, u1 >= 0.f ? u1 : a * u1,
                u2 >= 0.f ? u2 : a * u2, u3 >= 0.f ? u3 : a * u3);
            *(float4*)(yrow + n2) = make_float4(
                u4 >= 0.f ? u4 : a * u4, u5 >= 0.f ? u5 : a * u5,
                u6 >= 0.f ? u6 : a * u6, u7 >= 0.f ? u7 : a * u7);
        }
    }
}

// ---------------------------------------------------------------------------
// Head GEMM: P = y @ [W_mu | W_std]   (M=40960, N=64, K=512)
// ---------------------------------------------------------------------------
__global__ __launch_bounds__(256) void k_mustd() {
    __shared__ __align__(16) float As[2][32][128];
    __shared__ __align__(16) float Bs[2][32][64];
    const int tid = threadIdx.x, ty = tid >> 4, tx = tid & 15;
    const int bm = blockIdx.y * 128;
    ull acc[4][4] = {};
    auto loadA = [&](int k0, int idx) -> float4 {
        int row = idx >> 3, kq = (idx & 7) * 4;
        return *(const float4*)(g_y + (size_t)(bm + row) * Hdim + k0 + kq);
    };
    run_gemm1<128>(acc, loadA, g_Bcomb, 64, 0, Hdim, As, Bs, tid);
    const int n = tx * 4;
#pragma unroll
    for (int p = 0; p < 4; p++) {
        float lo[4], hi[4];
#pragma unroll
        for (int c = 0; c < 4; c++) f32x2_unpack(acc[p][c], lo[c], hi[c]);
        int m0 = bm + ty * 8 + 2 * p;
        *(float4*)(g_p + (size_t)m0 * 64 + n) = make_float4(lo[0], lo[1], lo[2], lo[3]);
        *(float4*)(g_p + (size_t)(m0 + 1) * 64 + n) = make_float4(hi[0], hi[1], hi[2], hi[3]);
    }
}

// ---------------------------------------------------------------------------
// Tail: reparameterized sample, tanh, log_prob means. One block per b.
// ---------------------------------------------------------------------------
__global__ __launch_bounds__(256) void k_tail(const float* __restrict__ bmu,
                                              const float* __restrict__ bstd,
                                              const float* __restrict__ eps,
                                              float* __restrict__ out) {
    constexpr float STD_MIN = 2.0611536e-09f;
    constexpr float STD_MAX = 7.389056f;
    constexpr float HALF_LOG2PI = 0.9189385332046727f;
    const int b = blockIdx.x;
    const int tid = threadIdx.x;
    __shared__ float red[256];
    float lpsum = 0.0f;
    for (int idx = tid; idx < Ldim * Cdim; idx += 256) {
        int l = idx >> 5;
        int c = idx & 31;
        int row = b * Ldim + l;
        float mu = g_p[(size_t)row * 64 + c] + bmu[c];
        float sr = g_p[(size_t)row * 64 + 32 + c] + bstd[c];
        float sp = fmaxf(sr, 0.0f) + log1pf(expf(-fabsf(sr)));
        float sd = fminf(fmaxf(sp, STD_MIN), STD_MAX);
        float e  = eps[(size_t)row * Cdim + c];
        float comm = mu + e * sd;
        float co = tanhf(comm);
        out[(size_t)row * Cdim + c] = co;
        lpsum += -0.5f * e * e - logf(sd) - HALF_LOG2PI
                 - logf(1.0f - co * co + 1e-6f);
    }
    red[tid] = lpsum;
    __syncthreads();
    for (int s = 128; s > 0; s >>= 1) {
        if (tid < s) red[tid] += red[tid + s];
        __syncthreads();
    }
    if (tid == 0)
        out[OUT_CO + b] = red[0] * (1.0f / (Ldim * Cdim));
}

// ---------------------------------------------------------------------------
// Launch
// ---------------------------------------------------------------------------
extern "C" void kernel_launch(void* const* d_in, const int* in_sizes, int n_in,
                              void* d_out, int out_size) {
    const float* x    = (const float*)d_in[0];
    const float* Wr   = (const float*)d_in[1];
    const float* br   = (const float*)d_in[2];
    const float* Wz   = (const float*)d_in[3];
    const float* bz   = (const float*)d_in[4];
    const float* Wn   = (const float*)d_in[5];
    const float* bnn  = (const float*)d_in[6];
    const float* w1   = (const float*)d_in[7];
    const float* cb1  = (const float*)d_in[8];
    const float* w3   = (const float*)d_in[9];
    const float* cb3  = (const float*)d_in[10];
    const float* w5   = (const float*)d_in[11];
    const float* cb5  = (const float*)d_in[12];
    const float* w7   = (const float*)d_in[13];
    const float* cb7  = (const float*)d_in[14];
    const float* pa   = (const float*)d_in[15];
    const float* Wmu  = (const float*)d_in[16];
    const float* bmu  = (const float*)d_in[17];
    const float* Wstd = (const float*)d_in[18];
    const float* bstd = (const float*)d_in[19];
    const float* eps  = (const float*)d_in[20];
    float* out = (float*)d_out;

    k_pack<<<256, 256>>>(w1, w3, w5, w7, Wmu, Wstd);
    k_pre<<<dim3(24, 16), 256>>>(x, Wr, br, Wz, bz, Wn, bnn);
    k_step0<<<512, 256>>>();
    for (int t = 1; t < Ldim; t++) {
        k_rz<<<dim3(16, 16), 256>>>(Wr, Wz, t - 1);
        k_n <<<dim3(8, 32),  256>>>(Wn, t);
    }
    k_conv<<<dim3(4, 320), 256>>>(cb1, cb3, cb5, cb7, pa);
    k_mustd<<<dim3(1, 320), 256>>>();
    k_tail<<<Bdim, 256>>>(bmu, bstd, eps, out);
}

// round 16
// speedup vs baseline: 1.0646x; 1.0646x over previous
#include <cuda_runtime.h>
#include <math.h>

// ---------------------------------------------------------------------------
// Problem constants
// ---------------------------------------------------------------------------
constexpr int Hdim = 512;              // hidden
constexpr int Bdim = 2048;             // E*S
constexpr int Ldim = 20;               // comm steps
constexpr int Cdim = 32;               // comm shape
constexpr int OUT_CO = Bdim * Ldim * Cdim;

// ---------------------------------------------------------------------------
// Scratch (device globals -- no allocation allowed)
// ---------------------------------------------------------------------------
__device__ float g_ax[Bdim * Hdim];
__device__ float g_az[Bdim * Hdim];
__device__ float g_an[Bdim * Hdim];
__device__ float g_z [Bdim * Hdim];
__device__ float g_rh[Bdim * Hdim];
__device__ float g_hsT[Bdim * Ldim * Hdim];   // (B, L, H) hidden states
__device__ float g_y  [Bdim * Ldim * Hdim];   // conv output (B, L, 512)
__device__ float g_convB[16 * Hdim * 128];    // repacked conv weights, slot-major
__device__ float g_Bcomb[Hdim * 64];          // [W_mu | W_std]
__device__ float g_Brz[Hdim * 1024];          // [Wr_h | Wz_h]  (512 x 1024)
__device__ float g_part[2 * Bdim * 1024];     // split-K partials for r/z GEMM
__device__ float g_p[Bdim * Ldim * 64];

// ---------------------------------------------------------------------------
// Helpers
// ---------------------------------------------------------------------------
__device__ __forceinline__ float sigm(float x) { return 1.0f / (1.0f + expf(-x)); }

typedef unsigned long long ull;

__device__ __forceinline__ ull f32x2_dup(float a) {
    ull r; asm("mov.b64 %0, {%1, %1};" : "=l"(r) : "f"(a)); return r;
}
__device__ __forceinline__ ull fma2(ull a, ull b, ull c) {
    ull d; asm("fma.rn.f32x2 %0, %1, %2, %3;" : "=l"(d) : "l"(a), "l"(b), "l"(c));
    return d;
}
__device__ __forceinline__ void f32x2_unpack(ull v, float& lo, float& hi) {
    asm("mov.b64 {%0, %1}, %2;" : "=f"(lo), "=f"(hi) : "l"(v));
}

// ===========================================================================
// Core 1 (BK=32): 128 x 64 tile, 256 threads, thread tile 8x4 (4 row-pairs).
// A chunk map: idx = tid*4+i -> row = idx>>3, kq = (idx&7)*4.
// B chunk map: i in {0,1} -> kr = (tid>>4)+16*i, nq = (tid&15)*4.
// ===========================================================================
__device__ __forceinline__ void gemm_compute1(ull (&acc)[4][4],
                                              const float (&As)[32][128],
                                              const float (&Bs)[32][64],
                                              int ty, int tx) {
#pragma unroll
    for (int kk = 0; kk < 32; kk++) {
        ulonglong2 a01 = *(const ulonglong2*)&As[kk][ty * 8];
        ulonglong2 a23 = *(const ulonglong2*)&As[kk][ty * 8 + 4];
        ull a[4] = {a01.x, a01.y, a23.x, a23.y};
        float4 b = *(const float4*)&Bs[kk][tx * 4];
        ull bd[4] = {f32x2_dup(b.x), f32x2_dup(b.y), f32x2_dup(b.z), f32x2_dup(b.w)};
#pragma unroll
        for (int p = 0; p < 4; p++)
#pragma unroll
            for (int c = 0; c < 4; c++)
                acc[p][c] = fma2(a[p], bd[c], acc[p][c]);
    }
}

__device__ __forceinline__ void store_frag1(float (&As)[32][128], float (&Bs)[32][64],
                                            const float4* ar, const float4* br, int tid) {
#pragma unroll
    for (int i = 0; i < 4; i++) {
        int idx = tid * 4 + i;
        int row = idx >> 3, kq = (idx & 7) * 4;
        As[kq + 0][row] = ar[i].x; As[kq + 1][row] = ar[i].y;
        As[kq + 2][row] = ar[i].z; As[kq + 3][row] = ar[i].w;
    }
    int kr = tid >> 4, nq = (tid & 15) * 4;
    *(float4*)&Bs[kr][nq]      = br[0];
    *(float4*)&Bs[kr + 16][nq] = br[1];
}

template<typename LA>
__device__ __forceinline__ void run_gemm1(ull (&acc)[4][4], LA loadA,
                                          const float* __restrict__ Bsrc, int ldb,
                                          int bn0, int K,
                                          float (&As)[2][32][128],
                                          float (&Bs)[2][32][64], int tid) {
    const int ty = tid >> 4, tx = tid & 15;
    const int kr = tid >> 4, nq = (tid & 15) * 4;
    float4 ar[4], br[2];
#pragma unroll
    for (int i = 0; i < 4; i++) ar[i] = loadA(0, tid * 4 + i);
#pragma unroll
    for (int i = 0; i < 2; i++)
        br[i] = *(const float4*)(Bsrc + (size_t)(kr + 16 * i) * ldb + bn0 + nq);
    store_frag1(As[0], Bs[0], ar, br, tid);
    __syncthreads();
    int buf = 0;
    for (int k0 = 32; k0 < K; k0 += 32) {
#pragma unroll
        for (int i = 0; i < 4; i++) ar[i] = loadA(k0, tid * 4 + i);
#pragma unroll
        for (int i = 0; i < 2; i++)
            br[i] = *(const float4*)(Bsrc + (size_t)(k0 + kr + 16 * i) * ldb + bn0 + nq);
        gemm_compute1(acc, As[buf], Bs[buf], ty, tx);
        store_frag1(As[buf ^ 1], Bs[buf ^ 1], ar, br, tid);
        buf ^= 1;
        __syncthreads();
    }
    gemm_compute1(acc, As[buf], Bs[buf], ty, tx);
}

// ===========================================================================
// Core 2 (BK=16): 128 x 128 tile, 256 threads, thread tile 8x8.
// ===========================================================================
__device__ __forceinline__ void gemm_compute8(ull (&acc)[4][8],
                                              const float (&As)[16][128],
                                              const float (&Bs)[16][128],
                                              int ty, int tx) {
#pragma unroll
    for (int kk = 0; kk < 16; kk++) {
        ulonglong2 a01 = *(const ulonglong2*)&As[kk][ty * 8];
        ulonglong2 a23 = *(const ulonglong2*)&As[kk][ty * 8 + 4];
        ull a[4] = {a01.x, a01.y, a23.x, a23.y};
        {
            float4 b0 = *(const float4*)&Bs[kk][tx * 4];
            ull bd[4] = {f32x2_dup(b0.x), f32x2_dup(b0.y),
                         f32x2_dup(b0.z), f32x2_dup(b0.w)};
#pragma unroll
            for (int p = 0; p < 4; p++)
#pragma unroll
                for (int c = 0; c < 4; c++)
                    acc[p][c] = fma2(a[p], bd[c], acc[p][c]);
        }
        {
            float4 b1 = *(const float4*)&Bs[kk][64 + tx * 4];
            ull bd[4] = {f32x2_dup(b1.x), f32x2_dup(b1.y),
                         f32x2_dup(b1.z), f32x2_dup(b1.w)};
#pragma unroll
            for (int p = 0; p < 4; p++)
#pragma unroll
                for (int c = 0; c < 4; c++)
                    acc[p][4 + c] = fma2(a[p], bd[c], acc[p][4 + c]);
        }
    }
}

__device__ __forceinline__ void store_frag8(float (&As)[16][128], float (&Bs)[16][128],
                                            const float4* ar, const float4* br, int tid) {
#pragma unroll
    for (int i = 0; i < 2; i++) {
        int idx = tid * 2 + i;
        int row = idx >> 2, kq = (idx & 3) * 4;
        As[kq + 0][row] = ar[i].x; As[kq + 1][row] = ar[i].y;
        As[kq + 2][row] = ar[i].z; As[kq + 3][row] = ar[i].w;
    }
    int kr = tid >> 4, nq = (tid & 15) * 8;
    *(float4*)&Bs[kr][nq]     = br[0];
    *(float4*)&Bs[kr][nq + 4] = br[1];
}

template<typename LA>
__device__ __forceinline__ void run_gemm8(ull (&acc)[4][8], LA loadA,
                                          const float* __restrict__ Bsrc, int ldb,
                                          int bn0, int K,
                                          float (&As)[2][16][128],
                                          float (&Bs)[2][16][128], int tid) {
    const int ty = tid >> 4, tx = tid & 15;
    const int kr = tid >> 4, nq = (tid & 15) * 8;
    float4 ar[2], br[2];
#pragma unroll
    for (int i = 0; i < 2; i++) ar[i] = loadA(0, tid * 2 + i);
    br[0] = *(const float4*)(Bsrc + (size_t)kr * ldb + bn0 + nq);
    br[1] = *(const float4*)(Bsrc + (size_t)kr * ldb + bn0 + nq + 4);
    store_frag8(As[0], Bs[0], ar, br, tid);
    __syncthreads();
    int buf = 0;
    for (int k0 = 16; k0 < K; k0 += 16) {
#pragma unroll
        for (int i = 0; i < 2; i++) ar[i] = loadA(k0, tid * 2 + i);
        br[0] = *(const float4*)(Bsrc + (size_t)(k0 + kr) * ldb + bn0 + nq);
        br[1] = *(const float4*)(Bsrc + (size_t)(k0 + kr) * ldb + bn0 + nq + 4);
        gemm_compute8(acc, As[buf], Bs[buf], ty, tx);
        store_frag8(As[buf ^ 1], Bs[buf ^ 1], ar, br, tid);
        buf ^= 1;
        __syncthreads();
    }
    gemm_compute8(acc, As[buf], Bs[buf], ty, tx);
}

// ---------------------------------------------------------------------------
// Weight repack: conv slot-major; [W_mu|W_std]; [Wr_h|Wz_h]
// ---------------------------------------------------------------------------
__global__ void k_pack(const float* __restrict__ w1, const float* __restrict__ w3,
                       const float* __restrict__ w5, const float* __restrict__ w7,
                       const float* __restrict__ Wmu, const float* __restrict__ Wstd,
                       const float* __restrict__ Wr, const float* __restrict__ Wz) {
    const int totalConv = 16 * Hdim * 128;          // 1048576
    const int totalComb = Hdim * 64;                // 32768
    const int totalRZ   = Hdim * 1024;              // 524288
    const int total = totalConv + totalComb + totalRZ;
    for (int idx = blockIdx.x * blockDim.x + threadIdx.x;
         idx < total; idx += gridDim.x * blockDim.x) {
        if (idx < totalConv) {
            int slot = idx >> 16;
            int rem  = idx & 65535;
            int c    = rem >> 7;
            int o    = rem & 127;
            const float* w; int kg, j;
            if (slot == 0)      { w = w1; kg = 1; j = 0; }
            else if (slot < 4)  { w = w3; kg = 3; j = slot - 1; }
            else if (slot < 9)  { w = w5; kg = 5; j = slot - 4; }
            else                { w = w7; kg = 7; j = slot - 9; }
            g_convB[idx] = w[(size_t)o * Hdim * kg + c * kg + j];
        } else if (idx < totalConv + totalComb) {
            int i2 = idx - totalConv;
            int k = i2 >> 6;
            int n = i2 & 63;
            g_Bcomb[i2] = (n < 32) ? Wmu[k * 32 + n] : Wstd[k * 32 + (n - 32)];
        } else {
            int i3 = idx - totalConv - totalComb;
            int k = i3 >> 10;          // 0..511
            int n = i3 & 1023;         // 0..1023
            g_Brz[i3] = (n < 512) ? Wr[(size_t)(Hdim + k) * Hdim + n]
                                  : Wz[(size_t)(Hdim + k) * Hdim + (n - 512)];
        }
    }
}

// ---------------------------------------------------------------------------
// Precompute ax/az/an = xf @ W*[:H] + b*   (M=2048, N=1536, K=512)
// ---------------------------------------------------------------------------
__global__ __launch_bounds__(256) void k_pre(const float* __restrict__ x,
        const float* __restrict__ Wr, const float* __restrict__ br,
        const float* __restrict__ Wz, const float* __restrict__ bz,
        const float* __restrict__ Wn, const float* __restrict__ bnn) {
    __shared__ __align__(16) float As[2][32][128];
    __shared__ __align__(16) float Bs[2][32][64];
    const int tid = threadIdx.x, ty = tid >> 4, tx = tid & 15;
    const int bm = blockIdx.y * 128;
    const int bncol = blockIdx.x * 64;
    const int sel = bncol >> 9;
    const int nloc = bncol & 511;
    const float* W    = sel == 0 ? Wr : (sel == 1 ? Wz : Wn);
    const float* bias = sel == 0 ? br : (sel == 1 ? bz : bnn);
    float* out        = sel == 0 ? g_ax : (sel == 1 ? g_az : g_an);
    ull acc[4][4] = {};
    auto loadA = [&](int k0, int idx) -> float4 {
        int row = idx >> 3, kq = (idx & 7) * 4;
        return *(const float4*)(x + (size_t)(bm + row) * Hdim + k0 + kq);
    };
    run_gemm1(acc, loadA, W, Hdim, nloc, Hdim, As, Bs, tid);
    const int n = nloc + tx * 4;
    float4 bv = *(const float4*)(bias + n);
#pragma unroll
    for (int p = 0; p < 4; p++) {
        float lo[4], hi[4];
#pragma unroll
        for (int c = 0; c < 4; c++) f32x2_unpack(acc[p][c], lo[c], hi[c]);
        int m0 = bm + ty * 8 + 2 * p;
        *(float4*)(out + (size_t)m0 * Hdim + n) =
            make_float4(lo[0] + bv.x, lo[1] + bv.y, lo[2] + bv.z, lo[3] + bv.w);
        *(float4*)(out + (size_t)(m0 + 1) * Hdim + n) =
            make_float4(hi[0] + bv.x, hi[1] + bv.y, hi[2] + bv.z, hi[3] + bv.w);
    }
}

// ---------------------------------------------------------------------------
// Step 0 (h=0): h1 = (1 - sigmoid(az)) * tanh(an)  ->  hsT[:, 0, :]
// ---------------------------------------------------------------------------
__global__ void k_step0() {
    for (int i = blockIdx.x * blockDim.x + threadIdx.x; i < Bdim * Hdim;
         i += gridDim.x * blockDim.x) {
        float z = sigm(g_az[i]);
        float hn = (1.0f - z) * tanhf(g_an[i]);
        int m = i >> 9, n = i & 511;
        g_hsT[(size_t)m * (Ldim * Hdim) + n] = hn;
    }
}

// ---------------------------------------------------------------------------
// Recurrence phase A: split-K r/z GEMM partials.
// grid (8 N-tiles, 16 M-tiles, 2 K-halves) = 256 CTAs, core2 128x128xK=256.
// ---------------------------------------------------------------------------
__global__ __launch_bounds__(256) void k_rzA(int tm1) {
    __shared__ __align__(16) float As[2][16][128];
    __shared__ __align__(16) float Bs[2][16][128];
    const int tid = threadIdx.x, ty = tid >> 4, tx = tid & 15;
    const int bn = blockIdx.x * 128;
    const int bm = blockIdx.y * 128;
    const int kh = blockIdx.z;
    const int kbase = kh * 256;
    const float* Ab = g_hsT + (size_t)tm1 * Hdim + kbase;
    const float* Bsrc = g_Brz + (size_t)kbase * 1024;
    float* P = g_part + (size_t)kh * (Bdim * 1024);
    ull acc[4][8] = {};
    auto loadA = [&](int k0, int idx) -> float4 {
        int row = idx >> 2, kq = (idx & 3) * 4;
        return *(const float4*)(Ab + (size_t)(bm + row) * (Ldim * Hdim) + k0 + kq);
    };
    run_gemm8(acc, loadA, Bsrc, 1024, bn, 256, As, Bs, tid);
    const int n1 = bn + tx * 4;
    const int n2 = bn + 64 + tx * 4;
#pragma unroll
    for (int p = 0; p < 4; p++) {
        float lo[8], hi[8];
#pragma unroll
        for (int c = 0; c < 8; c++) f32x2_unpack(acc[p][c], lo[c], hi[c]);
        int m0 = bm + ty * 8 + 2 * p;
#pragma unroll
        for (int s = 0; s < 2; s++) {
            const float* v = s ? hi : lo;
            float* row = P + (size_t)(m0 + s) * 1024;
            *(float4*)(row + n1) = make_float4(v[0], v[1], v[2], v[3]);
            *(float4*)(row + n2) = make_float4(v[4], v[5], v[6], v[7]);
        }
    }
}

// ---------------------------------------------------------------------------
// Recurrence phase B: reduce split-K halves + sigmoid epilogues -> rh, z
// ---------------------------------------------------------------------------
__global__ __launch_bounds__(256) void k_rzB(int tm1) {
    const int total4 = Bdim * 1024 / 4;   // 524288 float4 groups
    for (int i = blockIdx.x * 256 + threadIdx.x; i < total4;
         i += gridDim.x * 256) {
        int m = i >> 8;
        int nq = (i & 255) * 4;
        float4 p0 = *(const float4*)(g_part + (size_t)m * 1024 + nq);
        float4 p1 = *(const float4*)(g_part + (size_t)(Bdim + m) * 1024 + nq);
        float4 sv = make_float4(p0.x + p1.x, p0.y + p1.y, p0.z + p1.z, p0.w + p1.w);
        if (nq < 512) {
            size_t base = (size_t)m * Hdim + nq;
            float4 ax = *(const float4*)(g_ax + base);
            float4 hv = *(const float4*)(g_hsT + ((size_t)m * Ldim + tm1) * Hdim + nq);
            *(float4*)(g_rh + base) = make_float4(
                sigm(ax.x + sv.x) * hv.x, sigm(ax.y + sv.y) * hv.y,
                sigm(ax.z + sv.z) * hv.z, sigm(ax.w + sv.w) * hv.w);
        } else {
            size_t base = (size_t)m * Hdim + (nq - 512);
            float4 az = *(const float4*)(g_az + base);
            *(float4*)(g_z + base) = make_float4(
                sigm(az.x + sv.x), sigm(az.y + sv.y),
                sigm(az.z + sv.z), sigm(az.w + sv.w));
        }
    }
}

// ---------------------------------------------------------------------------
// Recurrence: n GEMM + state update  (M=2048, N=512, K=512), 128x64, 128 CTAs
// ---------------------------------------------------------------------------
__global__ __launch_bounds__(256) void k_n(const float* __restrict__ Wn, int t) {
    __shared__ __align__(16) float As[2][32][128];
    __shared__ __align__(16) float Bs[2][32][64];
    const int tid = threadIdx.x, ty = tid >> 4, tx = tid & 15;
    const int bm = blockIdx.y * 128;
    const int bncol = blockIdx.x * 64;
    const int tm1 = t - 1;
    const float* W = Wn + (size_t)Hdim * Hdim;
    ull acc[4][4] = {};
    auto loadA = [&](int k0, int idx) -> float4 {
        int row = idx >> 3, kq = (idx & 7) * 4;
        return *(const float4*)(g_rh + (size_t)(bm + row) * Hdim + k0 + kq);
    };
    run_gemm1(acc, loadA, W, Hdim, bncol, Hdim, As, Bs, tid);
    const int n = bncol + tx * 4;
#pragma unroll
    for (int p = 0; p < 4; p++) {
        float lo[4], hi[4];
#pragma unroll
        for (int c = 0; c < 4; c++) f32x2_unpack(acc[p][c], lo[c], hi[c]);
        int m0 = bm + ty * 8 + 2 * p;
#pragma unroll
        for (int s = 0; s < 2; s++) {
            int m = m0 + s;
            float a0 = s ? hi[0] : lo[0], a1 = s ? hi[1] : lo[1];
            float a2 = s ? hi[2] : lo[2], a3 = s ? hi[3] : lo[3];
            size_t base = (size_t)m * Hdim + n;
            float4 anv = *(const float4*)(g_an + base);
            float4 zv  = *(const float4*)(g_z + base);
            float4 hv  = *(const float4*)(g_hsT + ((size_t)m * Ldim + tm1) * Hdim + n);
            float nn0 = tanhf(anv.x + a0), nn1 = tanhf(anv.y + a1);
            float nn2 = tanhf(anv.z + a2), nn3 = tanhf(anv.w + a3);
            *(float4*)(g_hsT + ((size_t)m * Ldim + t) * Hdim + n) = make_float4(
                (1.0f - zv.x) * nn0 + zv.x * hv.x, (1.0f - zv.y) * nn1 + zv.y * hv.y,
                (1.0f - zv.z) * nn2 + zv.z * hv.z, (1.0f - zv.w) * nn3 + zv.w * hv.w);
        }
    }
}

// ---------------------------------------------------------------------------
// Multi-scale conv (4 groups, blockIdx.z = group), tap-shifted GEMM.
// 128(M) x 128(N = whole group) tiles, 8x8 thread tile. PReLU fused. (R13)
// ---------------------------------------------------------------------------
__global__ __launch_bounds__(256) void k_conv(const float* __restrict__ cb1,
                                              const float* __restrict__ cb3,
                                              const float* __restrict__ cb5,
                                              const float* __restrict__ cb7,
                                              const float* __restrict__ prelu_a) {
    __shared__ __align__(16) float As[2][16][128];
    __shared__ __align__(16) float Bs[2][16][128];
    const int tid = threadIdx.x, ty = tid >> 4, tx = tid & 15;
    const int g = blockIdx.z;
    const int taps = 2 * g + 1;
    const int pad  = g;
    const int slotBase[4] = {0, 1, 4, 9};
    const int colOff = g * 128;
    const float* bias = g == 0 ? cb1 : (g == 1 ? cb3 : (g == 2 ? cb5 : cb7));
    const int bm = blockIdx.y * 128;
    const float* Bsrc = g_convB + (size_t)slotBase[g] * 65536;
    const int K = taps * Hdim;
    int rowi[2], li[2];
#pragma unroll
    for (int i = 0; i < 2; i++) {
        int idx = tid * 2 + i;
        rowi[i] = bm + (idx >> 2);
        li[i] = rowi[i] % Ldim;
    }
    ull acc[4][8] = {};
    auto loadA = [&](int k0, int idx) -> float4 {
        int i = idx & 1;
        int kq = (idx & 3) * 4;
        int j = k0 >> 9;
        int dl = j - pad;
        int c = (k0 & 511) + kq;
        int lp = li[i] + dl;
        float4 v = make_float4(0.f, 0.f, 0.f, 0.f);
        if (lp >= 0 && lp < Ldim)
            v = *(const float4*)(g_hsT + (size_t)(rowi[i] + dl) * Hdim + c);
        return v;
    };
    run_gemm8(acc, loadA, Bsrc, 128, 0, K, As, Bs, tid);
    const float a = *prelu_a;
    const int n1 = tx * 4;
    const int n2 = 64 + tx * 4;
    float4 bv1 = *(const float4*)(bias + n1);
    float4 bv2 = *(const float4*)(bias + n2);
#pragma unroll
    for (int p = 0; p < 4; p++) {
        float lo[8], hi[8];
#pragma unroll
        for (int c = 0; c < 8; c++) f32x2_unpack(acc[p][c], lo[c], hi[c]);
        int m0 = bm + ty * 8 + 2 * p;
#pragma unroll
        for (int s = 0; s < 2; s++) {
            const float* v = s ? hi : lo;
            float* yrow = g_y + (size_t)(m0 + s) * Hdim + colOff;
            float u0 = v[0] + bv1.x, u1 = v[1] + bv1.y;
            float u2 = v[2] + bv1.z, u3 = v[3] + bv1.w;
            float u4 = v[4] + bv2.x, u5 = v[5] + bv2.y;
            float u6 = v[6] + bv2.z, u7 = v[7] + bv2.w;
            *(float4*)(yrow + n1) = make_float4(
                u0 >= 0.f ? u0 : a * u0, u1 >= 0.f ? u1 : a * u1,
                u2 >= 0.f ? u2 : a * u2, u3 >= 0.f ? u3 : a * u3);
            *(float4*)(yrow + n2) = make_float4(
                u4 >= 0.f ? u4 : a * u4, u5 >= 0.f ? u5 : a * u5,
                u6 >= 0.f ? u6 : a * u6, u7 >= 0.f ? u7 : a * u7);
        }
    }
}

// ---------------------------------------------------------------------------
// Head GEMM: P = y @ [W_mu | W_std]   (M=40960, N=64, K=512)
// ---------------------------------------------------------------------------
__global__ __launch_bounds__(256) void k_mustd() {
    __shared__ __align__(16) float As[2][32][128];
    __shared__ __align__(16) float Bs[2][32][64];
    const int tid = threadIdx.x, ty = tid >> 4, tx = tid & 15;
    const int bm = blockIdx.y * 128;
    ull acc[4][4] = {};
    auto loadA = [&](int k0, int idx) -> float4 {
        int row = idx >> 3, kq = (idx & 7) * 4;
        return *(const float4*)(g_y + (size_t)(bm + row) * Hdim + k0 + kq);
    };
    run_gemm1(acc, loadA, g_Bcomb, 64, 0, Hdim, As, Bs, tid);
    const int n = tx * 4;
#pragma unroll
    for (int p = 0; p < 4; p++) {
        float lo[4], hi[4];
#pragma unroll
        for (int c = 0; c < 4; c++) f32x2_unpack(acc[p][c], lo[c], hi[c]);
        int m0 = bm + ty * 8 + 2 * p;
        *(float4*)(g_p + (size_t)m0 * 64 + n) = make_float4(lo[0], lo[1], lo[2], lo[3]);
        *(float4*)(g_p + (size_t)(m0 + 1) * 64 + n) = make_float4(hi[0], hi[1], hi[2], hi[3]);
    }
}

// ---------------------------------------------------------------------------
// Tail: reparameterized sample, tanh, log_prob means. One block per b.
// ---------------------------------------------------------------------------
__global__ __launch_bounds__(256) void k_tail(const float* __restrict__ bmu,
                                              const float* __restrict__ bstd,
                                              const float* __restrict__ eps,
                                              float* __restrict__ out) {
    constexpr float STD_MIN = 2.0611536e-09f;
    constexpr float STD_MAX = 7.389056f;
    constexpr float HALF_LOG2PI = 0.9189385332046727f;
    const int b = blockIdx.x;
    const int tid = threadIdx.x;
    __shared__ float red[256];
    float lpsum = 0.0f;
    for (int idx = tid; idx < Ldim * Cdim; idx += 256) {
        int l = idx >> 5;
        int c = idx & 31;
        int row = b * Ldim + l;
        float mu = g_p[(size_t)row * 64 + c] + bmu[c];
        float sr = g_p[(size_t)row * 64 + 32 + c] + bstd[c];
        float sp = fmaxf(sr, 0.0f) + log1pf(expf(-fabsf(sr)));
        float sd = fminf(fmaxf(sp, STD_MIN), STD_MAX);
        float e  = eps[(size_t)row * Cdim + c];
        float comm = mu + e * sd;
        float co = tanhf(comm);
        out[(size_t)row * Cdim + c] = co;
        lpsum += -0.5f * e * e - logf(sd) - HALF_LOG2PI
                 - logf(1.0f - co * co + 1e-6f);
    }
    red[tid] = lpsum;
    __syncthreads();
    for (int s = 128; s > 0; s >>= 1) {
        if (tid < s) red[tid] += red[tid + s];
        __syncthreads();
    }
    if (tid == 0)
        out[OUT_CO + b] = red[0] * (1.0f / (Ldim * Cdim));
}

// ---------------------------------------------------------------------------
// Launch
// ---------------------------------------------------------------------------
extern "C" void kernel_launch(void* const* d_in, const int* in_sizes, int n_in,
                              void* d_out, int out_size) {
    const float* x    = (const float*)d_in[0];
    const float* Wr   = (const float*)d_in[1];
    const float* br   = (const float*)d_in[2];
    const float* Wz   = (const float*)d_in[3];
    const float* bz   = (const float*)d_in[4];
    const float* Wn   = (const float*)d_in[5];
    const float* bnn  = (const float*)d_in[6];
    const float* w1   = (const float*)d_in[7];
    const float* cb1  = (const float*)d_in[8];
    const float* w3   = (const float*)d_in[9];
    const float* cb3  = (const float*)d_in[10];
    const float* w5   = (const float*)d_in[11];
    const float* cb5  = (const float*)d_in[12];
    const float* w7   = (const float*)d_in[13];
    const float* cb7  = (const float*)d_in[14];
    const float* pa   = (const float*)d_in[15];
    const float* Wmu  = (const float*)d_in[16];
    const float* bmu  = (const float*)d_in[17];
    const float* Wstd = (const float*)d_in[18];
    const float* bstd = (const float*)d_in[19];
    const float* eps  = (const float*)d_in[20];
    float* out = (float*)d_out;

    k_pack<<<256, 256>>>(w1, w3, w5, w7, Wmu, Wstd, Wr, Wz);
    k_pre<<<dim3(24, 16), 256>>>(x, Wr, br, Wz, bz, Wn, bnn);
    k_step0<<<512, 256>>>();
    for (int t = 1; t < Ldim; t++) {
        k_rzA<<<dim3(8, 16, 2), 256>>>(t - 1);
        k_rzB<<<1024, 256>>>(t - 1);
        k_n  <<<dim3(8, 16),    256>>>(Wn, t);
    }
    k_conv<<<dim3(1, 320, 4), 256>>>(cb1, cb3, cb5, cb7, pa);
    k_mustd<<<dim3(1, 320), 256>>>();
    k_tail<<<Bdim, 256>>>(bmu, bstd, eps, out);
}

// round 17
// speedup vs baseline: 1.0716x; 1.0065x over previous
#include <cuda_runtime.h>
#include <math.h>

// ---------------------------------------------------------------------------
// Problem constants
// ---------------------------------------------------------------------------
constexpr int Hdim = 512;              // hidden
constexpr int Bdim = 2048;             // E*S
constexpr int Ldim = 20;               // comm steps
constexpr int Cdim = 32;               // comm shape
constexpr int OUT_CO = Bdim * Ldim * Cdim;

// ---------------------------------------------------------------------------
// Scratch (device globals -- no allocation allowed)
// ---------------------------------------------------------------------------
__device__ float g_ax[Bdim * Hdim];
__device__ float g_az[Bdim * Hdim];
__device__ float g_an[Bdim * Hdim];
__device__ float g_z [Bdim * Hdim];
__device__ float g_rh[Bdim * Hdim];
__device__ float g_hsT[Bdim * Ldim * Hdim];   // (B, L, H) hidden states
__device__ float g_y  [Bdim * Ldim * Hdim];   // conv output (B, L, 512)
__device__ float g_convB[16 * Hdim * 128];    // repacked conv weights, slot-major
__device__ float g_Bcomb[Hdim * 64];          // [W_mu | W_std]
__device__ float g_Brz[Hdim * 1024];          // [Wr_h | Wz_h]  (512 x 1024)
__device__ float g_part[2 * Bdim * 1024];     // split-K partials (rz: 2x2048x1024, n: 4x2048x512)
__device__ float g_p[Bdim * Ldim * 64];

// ---------------------------------------------------------------------------
// Helpers
// ---------------------------------------------------------------------------
__device__ __forceinline__ float sigm(float x) { return 1.0f / (1.0f + expf(-x)); }

typedef unsigned long long ull;

__device__ __forceinline__ ull f32x2_dup(float a) {
    ull r; asm("mov.b64 %0, {%1, %1};" : "=l"(r) : "f"(a)); return r;
}
__device__ __forceinline__ ull fma2(ull a, ull b, ull c) {
    ull d; asm("fma.rn.f32x2 %0, %1, %2, %3;" : "=l"(d) : "l"(a), "l"(b), "l"(c));
    return d;
}
__device__ __forceinline__ void f32x2_unpack(ull v, float& lo, float& hi) {
    asm("mov.b64 {%0, %1}, %2;" : "=f"(lo), "=f"(hi) : "l"(v));
}

// ===========================================================================
// Core 1 (BK=32): 128 x 64 tile, 256 threads, thread tile 8x4 (4 row-pairs).
// ===========================================================================
__device__ __forceinline__ void gemm_compute1(ull (&acc)[4][4],
                                              const float (&As)[32][128],
                                              const float (&Bs)[32][64],
                                              int ty, int tx) {
#pragma unroll
    for (int kk = 0; kk < 32; kk++) {
        ulonglong2 a01 = *(const ulonglong2*)&As[kk][ty * 8];
        ulonglong2 a23 = *(const ulonglong2*)&As[kk][ty * 8 + 4];
        ull a[4] = {a01.x, a01.y, a23.x, a23.y};
        float4 b = *(const float4*)&Bs[kk][tx * 4];
        ull bd[4] = {f32x2_dup(b.x), f32x2_dup(b.y), f32x2_dup(b.z), f32x2_dup(b.w)};
#pragma unroll
        for (int p = 0; p < 4; p++)
#pragma unroll
            for (int c = 0; c < 4; c++)
                acc[p][c] = fma2(a[p], bd[c], acc[p][c]);
    }
}

__device__ __forceinline__ void store_frag1(float (&As)[32][128], float (&Bs)[32][64],
                                            const float4* ar, const float4* br, int tid) {
#pragma unroll
    for (int i = 0; i < 4; i++) {
        int idx = tid * 4 + i;
        int row = idx >> 3, kq = (idx & 7) * 4;
        As[kq + 0][row] = ar[i].x; As[kq + 1][row] = ar[i].y;
        As[kq + 2][row] = ar[i].z; As[kq + 3][row] = ar[i].w;
    }
    int kr = tid >> 4, nq = (tid & 15) * 4;
    *(float4*)&Bs[kr][nq]      = br[0];
    *(float4*)&Bs[kr + 16][nq] = br[1];
}

template<typename LA>
__device__ __forceinline__ void run_gemm1(ull (&acc)[4][4], LA loadA,
                                          const float* __restrict__ Bsrc, int ldb,
                                          int bn0, int K,
                                          float (&As)[2][32][128],
                                          float (&Bs)[2][32][64], int tid) {
    const int ty = tid >> 4, tx = tid & 15;
    const int kr = tid >> 4, nq = (tid & 15) * 4;
    float4 ar[4], br[2];
#pragma unroll
    for (int i = 0; i < 4; i++) ar[i] = loadA(0, tid * 4 + i);
#pragma unroll
    for (int i = 0; i < 2; i++)
        br[i] = *(const float4*)(Bsrc + (size_t)(kr + 16 * i) * ldb + bn0 + nq);
    store_frag1(As[0], Bs[0], ar, br, tid);
    __syncthreads();
    int buf = 0;
    for (int k0 = 32; k0 < K; k0 += 32) {
#pragma unroll
        for (int i = 0; i < 4; i++) ar[i] = loadA(k0, tid * 4 + i);
#pragma unroll
        for (int i = 0; i < 2; i++)
            br[i] = *(const float4*)(Bsrc + (size_t)(k0 + kr + 16 * i) * ldb + bn0 + nq);
        gemm_compute1(acc, As[buf], Bs[buf], ty, tx);
        store_frag1(As[buf ^ 1], Bs[buf ^ 1], ar, br, tid);
        buf ^= 1;
        __syncthreads();
    }
    gemm_compute1(acc, As[buf], Bs[buf], ty, tx);
}

// ===========================================================================
// Core 2 (BK=16): 128 x 128 tile, 256 threads, thread tile 8x8.
// ===========================================================================
__device__ __forceinline__ void gemm_compute8(ull (&acc)[4][8],
                                              const float (&As)[16][128],
                                              const float (&Bs)[16][128],
                                              int ty, int tx) {
#pragma unroll
    for (int kk = 0; kk < 16; kk++) {
        ulonglong2 a01 = *(const ulonglong2*)&As[kk][ty * 8];
        ulonglong2 a23 = *(const ulonglong2*)&As[kk][ty * 8 + 4];
        ull a[4] = {a01.x, a01.y, a23.x, a23.y};
        {
            float4 b0 = *(const float4*)&Bs[kk][tx * 4];
            ull bd[4] = {f32x2_dup(b0.x), f32x2_dup(b0.y),
                         f32x2_dup(b0.z), f32x2_dup(b0.w)};
#pragma unroll
            for (int p = 0; p < 4; p++)
#pragma unroll
                for (int c = 0; c < 4; c++)
                    acc[p][c] = fma2(a[p], bd[c], acc[p][c]);
        }
        {
            float4 b1 = *(const float4*)&Bs[kk][64 + tx * 4];
            ull bd[4] = {f32x2_dup(b1.x), f32x2_dup(b1.y),
                         f32x2_dup(b1.z), f32x2_dup(b1.w)};
#pragma unroll
            for (int p = 0; p < 4; p++)
#pragma unroll
                for (int c = 0; c < 4; c++)
                    acc[p][4 + c] = fma2(a[p], bd[c], acc[p][4 + c]);
        }
    }
}

__device__ __forceinline__ void store_frag8(float (&As)[16][128], float (&Bs)[16][128],
                                            const float4* ar, const float4* br, int tid) {
#pragma unroll
    for (int i = 0; i < 2; i++) {
        int idx = tid * 2 + i;
        int row = idx >> 2, kq = (idx & 3) * 4;
        As[kq + 0][row] = ar[i].x; As[kq + 1][row] = ar[i].y;
        As[kq + 2][row] = ar[i].z; As[kq + 3][row] = ar[i].w;
    }
    int kr = tid >> 4, nq = (tid & 15) * 8;
    *(float4*)&Bs[kr][nq]     = br[0];
    *(float4*)&Bs[kr][nq + 4] = br[1];
}

template<typename LA>
__device__ __forceinline__ void run_gemm8(ull (&acc)[4][8], LA loadA,
                                          const float* __restrict__ Bsrc, int ldb,
                                          int bn0, int K,
                                          float (&As)[2][16][128],
                                          float (&Bs)[2][16][128], int tid) {
    const int ty = tid >> 4, tx = tid & 15;
    const int kr = tid >> 4, nq = (tid & 15) * 8;
    float4 ar[2], br[2];
#pragma unroll
    for (int i = 0; i < 2; i++) ar[i] = loadA(0, tid * 2 + i);
    br[0] = *(const float4*)(Bsrc + (size_t)kr * ldb + bn0 + nq);
    br[1] = *(const float4*)(Bsrc + (size_t)kr * ldb + bn0 + nq + 4);
    store_frag8(As[0], Bs[0], ar, br, tid);
    __syncthreads();
    int buf = 0;
    for (int k0 = 16; k0 < K; k0 += 16) {
#pragma unroll
        for (int i = 0; i < 2; i++) ar[i] = loadA(k0, tid * 2 + i);
        br[0] = *(const float4*)(Bsrc + (size_t)(k0 + kr) * ldb + bn0 + nq);
        br[1] = *(const float4*)(Bsrc + (size_t)(k0 + kr) * ldb + bn0 + nq + 4);
        gemm_compute8(acc, As[buf], Bs[buf], ty, tx);
        store_frag8(As[buf ^ 1], Bs[buf ^ 1], ar, br, tid);
        buf ^= 1;
        __syncthreads();
    }
    gemm_compute8(acc, As[buf], Bs[buf], ty, tx);
}

// ---------------------------------------------------------------------------
// Weight repack: conv slot-major; [W_mu|W_std]; [Wr_h|Wz_h]
// ---------------------------------------------------------------------------
__global__ void k_pack(const float* __restrict__ w1, const float* __restrict__ w3,
                       const float* __restrict__ w5, const float* __restrict__ w7,
                       const float* __restrict__ Wmu, const float* __restrict__ Wstd,
                       const float* __restrict__ Wr, const float* __restrict__ Wz) {
    const int totalConv = 16 * Hdim * 128;          // 1048576
    const int totalComb = Hdim * 64;                // 32768
    const int totalRZ   = Hdim * 1024;              // 524288
    const int total = totalConv + totalComb + totalRZ;
    for (int idx = blockIdx.x * blockDim.x + threadIdx.x;
         idx < total; idx += gridDim.x * blockDim.x) {
        if (idx < totalConv) {
            int slot = idx >> 16;
            int rem  = idx & 65535;
            int c    = rem >> 7;
            int o    = rem & 127;
            const float* w; int kg, j;
            if (slot == 0)      { w = w1; kg = 1; j = 0; }
            else if (slot < 4)  { w = w3; kg = 3; j = slot - 1; }
            else if (slot < 9)  { w = w5; kg = 5; j = slot - 4; }
            else                { w = w7; kg = 7; j = slot - 9; }
            g_convB[idx] = w[(size_t)o * Hdim * kg + c * kg + j];
        } else if (idx < totalConv + totalComb) {
            int i2 = idx - totalConv;
            int k = i2 >> 6;
            int n = i2 & 63;
            g_Bcomb[i2] = (n < 32) ? Wmu[k * 32 + n] : Wstd[k * 32 + (n - 32)];
        } else {
            int i3 = idx - totalConv - totalComb;
            int k = i3 >> 10;          // 0..511
            int n = i3 & 1023;         // 0..1023
            g_Brz[i3] = (n < 512) ? Wr[(size_t)(Hdim + k) * Hdim + n]
                                  : Wz[(size_t)(Hdim + k) * Hdim + (n - 512)];
        }
    }
}

// ---------------------------------------------------------------------------
// Precompute ax/az/an = xf @ W*[:H] + b*   (M=2048, N=1536, K=512)
// ---------------------------------------------------------------------------
__global__ __launch_bounds__(256) void k_pre(const float* __restrict__ x,
        const float* __restrict__ Wr, const float* __restrict__ br,
        const float* __restrict__ Wz, const float* __restrict__ bz,
        const float* __restrict__ Wn, const float* __restrict__ bnn) {
    __shared__ __align__(16) float As[2][32][128];
    __shared__ __align__(16) float Bs[2][32][64];
    const int tid = threadIdx.x, ty = tid >> 4, tx = tid & 15;
    const int bm = blockIdx.y * 128;
    const int bncol = blockIdx.x * 64;
    const int sel = bncol >> 9;
    const int nloc = bncol & 511;
    const float* W    = sel == 0 ? Wr : (sel == 1 ? Wz : Wn);
    const float* bias = sel == 0 ? br : (sel == 1 ? bz : bnn);
    float* out        = sel == 0 ? g_ax : (sel == 1 ? g_az : g_an);
    ull acc[4][4] = {};
    auto loadA = [&](int k0, int idx) -> float4 {
        int row = idx >> 3, kq = (idx & 7) * 4;
        return *(const float4*)(x + (size_t)(bm + row) * Hdim + k0 + kq);
    };
    run_gemm1(acc, loadA, W, Hdim, nloc, Hdim, As, Bs, tid);
    const int n = nloc + tx * 4;
    float4 bv = *(const float4*)(bias + n);
#pragma unroll
    for (int p = 0; p < 4; p++) {
        float lo[4], hi[4];
#pragma unroll
        for (int c = 0; c < 4; c++) f32x2_unpack(acc[p][c], lo[c], hi[c]);
        int m0 = bm + ty * 8 + 2 * p;
        *(float4*)(out + (size_t)m0 * Hdim + n) =
            make_float4(lo[0] + bv.x, lo[1] + bv.y, lo[2] + bv.z, lo[3] + bv.w);
        *(float4*)(out + (size_t)(m0 + 1) * Hdim + n) =
            make_float4(hi[0] + bv.x, hi[1] + bv.y, hi[2] + bv.z, hi[3] + bv.w);
    }
}

// ---------------------------------------------------------------------------
// Step 0 (h=0): h1 = (1 - sigmoid(az)) * tanh(an)  ->  hsT[:, 0, :]
// ---------------------------------------------------------------------------
__global__ void k_step0() {
    for (int i = blockIdx.x * blockDim.x + threadIdx.x; i < Bdim * Hdim;
         i += gridDim.x * blockDim.x) {
        float z = sigm(g_az[i]);
        float hn = (1.0f - z) * tanhf(g_an[i]);
        int m = i >> 9, n = i & 511;
        g_hsT[(size_t)m * (Ldim * Hdim) + n] = hn;
    }
}

// ---------------------------------------------------------------------------
// Recurrence phase A: split-K r/z GEMM partials.
// grid (8 N-tiles, 16 M-tiles, 2 K-halves) = 256 CTAs, core2 128x128xK=256.
// ---------------------------------------------------------------------------
__global__ __launch_bounds__(256) void k_rzA(int tm1) {
    __shared__ __align__(16) float As[2][16][128];
    __shared__ __align__(16) float Bs[2][16][128];
    const int tid = threadIdx.x, ty = tid >> 4, tx = tid & 15;
    const int bn = blockIdx.x * 128;
    const int bm = blockIdx.y * 128;
    const int kh = blockIdx.z;
    const int kbase = kh * 256;
    const float* Ab = g_hsT + (size_t)tm1 * Hdim + kbase;
    const float* Bsrc = g_Brz + (size_t)kbase * 1024;
    float* P = g_part + (size_t)kh * (Bdim * 1024);
    ull acc[4][8] = {};
    auto loadA = [&](int k0, int idx) -> float4 {
        int row = idx >> 2, kq = (idx & 3) * 4;
        return *(const float4*)(Ab + (size_t)(bm + row) * (Ldim * Hdim) + k0 + kq);
    };
    run_gemm8(acc, loadA, Bsrc, 1024, bn, 256, As, Bs, tid);
    const int n1 = bn + tx * 4;
    const int n2 = bn + 64 + tx * 4;
#pragma unroll
    for (int p = 0; p < 4; p++) {
        float lo[8], hi[8];
#pragma unroll
        for (int c = 0; c < 8; c++) f32x2_unpack(acc[p][c], lo[c], hi[c]);
        int m0 = bm + ty * 8 + 2 * p;
#pragma unroll
        for (int s = 0; s < 2; s++) {
            const float* v = s ? hi : lo;
            float* row = P + (size_t)(m0 + s) * 1024;
            *(float4*)(row + n1) = make_float4(v[0], v[1], v[2], v[3]);
            *(float4*)(row + n2) = make_float4(v[4], v[5], v[6], v[7]);
        }
    }
}

// ---------------------------------------------------------------------------
// Recurrence phase B: reduce split-K halves + sigmoid epilogues -> rh, z
// ---------------------------------------------------------------------------
__global__ __launch_bounds__(256) void k_rzB(int tm1) {
    const int total4 = Bdim * 1024 / 4;   // 524288 float4 groups
    for (int i = blockIdx.x * 256 + threadIdx.x; i < total4;
         i += gridDim.x * 256) {
        int m = i >> 8;
        int nq = (i & 255) * 4;
        float4 p0 = *(const float4*)(g_part + (size_t)m * 1024 + nq);
        float4 p1 = *(const float4*)(g_part + (size_t)(Bdim + m) * 1024 + nq);
        float4 sv = make_float4(p0.x + p1.x, p0.y + p1.y, p0.z + p1.z, p0.w + p1.w);
        if (nq < 512) {
            size_t base = (size_t)m * Hdim + nq;
            float4 ax = *(const float4*)(g_ax + base);
            float4 hv = *(const float4*)(g_hsT + ((size_t)m * Ldim + tm1) * Hdim + nq);
            *(float4*)(g_rh + base) = make_float4(
                sigm(ax.x + sv.x) * hv.x, sigm(ax.y + sv.y) * hv.y,
                sigm(ax.z + sv.z) * hv.z, sigm(ax.w + sv.w) * hv.w);
        } else {
            size_t base = (size_t)m * Hdim + (nq - 512);
            float4 az = *(const float4*)(g_az + base);
            *(float4*)(g_z + base) = make_float4(
                sigm(az.x + sv.x), sigm(az.y + sv.y),
                sigm(az.z + sv.z), sigm(az.w + sv.w));
        }
    }
}

// ---------------------------------------------------------------------------
// Recurrence phase A2: split-K n GEMM partials.
// grid (4 N-tiles, 16 M-tiles, 4 K-quarters) = 256 CTAs, core2 128x128xK=128.
// Partials into g_part (4 x 2048 x 512 floats = exact capacity reuse).
// ---------------------------------------------------------------------------
__global__ __launch_bounds__(256) void k_nA(const float* __restrict__ Wn) {
    __shared__ __align__(16) float As[2][16][128];
    __shared__ __align__(16) float Bs[2][16][128];
    const int tid = threadIdx.x, ty = tid >> 4, tx = tid & 15;
    const int bn = blockIdx.x * 128;
    const int bm = blockIdx.y * 128;
    const int kq4 = blockIdx.z;
    const int kbase = kq4 * 128;
    const float* Bsrc = Wn + (size_t)Hdim * Hdim + (size_t)kbase * Hdim;
    float* P = g_part + (size_t)kq4 * (Bdim * 512);
    ull acc[4][8] = {};
    auto loadA = [&](int k0, int idx) -> float4 {
        int row = idx >> 2, kq = (idx & 3) * 4;
        return *(const float4*)(g_rh + (size_t)(bm + row) * Hdim + kbase + k0 + kq);
    };
    run_gemm8(acc, loadA, Bsrc, Hdim, bn, 128, As, Bs, tid);
    const int n1 = bn + tx * 4;
    const int n2 = bn + 64 + tx * 4;
#pragma unroll
    for (int p = 0; p < 4; p++) {
        float lo[8], hi[8];
#pragma unroll
        for (int c = 0; c < 8; c++) f32x2_unpack(acc[p][c], lo[c], hi[c]);
        int m0 = bm + ty * 8 + 2 * p;
#pragma unroll
        for (int s = 0; s < 2; s++) {
            const float* v = s ? hi : lo;
            float* row = P + (size_t)(m0 + s) * 512;
            *(float4*)(row + n1) = make_float4(v[0], v[1], v[2], v[3]);
            *(float4*)(row + n2) = make_float4(v[4], v[5], v[6], v[7]);
        }
    }
}

// ---------------------------------------------------------------------------
// Recurrence phase B2: reduce 4 n-partials + tanh + GRU state update -> hsT[t]
// ---------------------------------------------------------------------------
__global__ __launch_bounds__(256) void k_nB(int t) {
    const int tm1 = t - 1;
    const int total4 = Bdim * Hdim / 4;   // 262144 float4 groups
    for (int i = blockIdx.x * 256 + threadIdx.x; i < total4;
         i += gridDim.x * 256) {
        int m = i >> 7;
        int nq = (i & 127) * 4;
        size_t off = (size_t)m * 512 + nq;
        float4 p0 = *(const float4*)(g_part + off);
        float4 p1 = *(const float4*)(g_part + (size_t)Bdim * 512 + off);
        float4 p2 = *(const float4*)(g_part + (size_t)2 * Bdim * 512 + off);
        float4 p3 = *(const float4*)(g_part + (size_t)3 * Bdim * 512 + off);
        float4 sv = make_float4(((p0.x + p1.x) + p2.x) + p3.x,
                                ((p0.y + p1.y) + p2.y) + p3.y,
                                ((p0.z + p1.z) + p2.z) + p3.z,
                                ((p0.w + p1.w) + p2.w) + p3.w);
        size_t base = (size_t)m * Hdim + nq;
        float4 anv = *(const float4*)(g_an + base);
        float4 zv  = *(const float4*)(g_z + base);
        float4 hv  = *(const float4*)(g_hsT + ((size_t)m * Ldim + tm1) * Hdim + nq);
        float nn0 = tanhf(anv.x + sv.x), nn1 = tanhf(anv.y + sv.y);
        float nn2 = tanhf(anv.z + sv.z), nn3 = tanhf(anv.w + sv.w);
        *(float4*)(g_hsT + ((size_t)m * Ldim + t) * Hdim + nq) = make_float4(
            (1.0f - zv.x) * nn0 + zv.x * hv.x, (1.0f - zv.y) * nn1 + zv.y * hv.y,
            (1.0f - zv.z) * nn2 + zv.z * hv.z, (1.0f - zv.w) * nn3 + zv.w * hv.w);
    }
}

// ---------------------------------------------------------------------------
// Multi-scale conv (4 groups, blockIdx.z = group), tap-shifted GEMM.
// 128(M) x 128(N = whole group) tiles, 8x8 thread tile. PReLU fused.
// ---------------------------------------------------------------------------
__global__ __launch_bounds__(256) void k_conv(const float* __restrict__ cb1,
                                              const float* __restrict__ cb3,
                                              const float* __restrict__ cb5,
                                              const float* __restrict__ cb7,
                                              const float* __restrict__ prelu_a) {
    __shared__ __align__(16) float As[2][16][128];
    __shared__ __align__(16) float Bs[2][16][128];
    const int tid = threadIdx.x, ty = tid >> 4, tx = tid & 15;
    const int g = blockIdx.z;
    const int taps = 2 * g + 1;
    const int pad  = g;
    const int slotBase[4] = {0, 1, 4, 9};
    const int colOff = g * 128;
    const float* bias = g == 0 ? cb1 : (g == 1 ? cb3 : (g == 2 ? cb5 : cb7));
    const int bm = blockIdx.y * 128;
    const float* Bsrc = g_convB + (size_t)slotBase[g] * 65536;
    const int K = taps * Hdim;
    int rowi[2], li[2];
#pragma unroll
    for (int i = 0; i < 2; i++) {
        int idx = tid * 2 + i;
        rowi[i] = bm + (idx >> 2);
        li[i] = rowi[i] % Ldim;
    }
    ull acc[4][8] = {};
    auto loadA = [&](int k0, int idx) -> float4 {
        int i = idx & 1;
        int kq = (idx & 3) * 4;
        int j = k0 >> 9;
        int dl = j - pad;
        int c = (k0 & 511) + kq;
        int lp = li[i] + dl;
        float4 v = make_float4(0.f, 0.f, 0.f, 0.f);
        if (lp >= 0 && lp < Ldim)
            v = *(const float4*)(g_hsT + (size_t)(rowi[i] + dl) * Hdim + c);
        return v;
    };
    run_gemm8(acc, loadA, Bsrc, 128, 0, K, As, Bs, tid);
    const float a = *prelu_a;
    const int n1 = tx * 4;
    const int n2 = 64 + tx * 4;
    float4 bv1 = *(const float4*)(bias + n1);
    float4 bv2 = *(const float4*)(bias + n2);
#pragma unroll
    for (int p = 0; p < 4; p++) {
        float lo[8], hi[8];
#pragma unroll
        for (int c = 0; c < 8; c++) f32x2_unpack(acc[p][c], lo[c], hi[c]);
        int m0 = bm + ty * 8 + 2 * p;
#pragma unroll
        for (int s = 0; s < 2; s++) {
            const float* v = s ? hi : lo;
            float* yrow = g_y + (size_t)(m0 + s) * Hdim + colOff;
            float u0 = v[0] + bv1.x, u1 = v[1] + bv1.y;
            float u2 = v[2] + bv1.z, u3 = v[3] + bv1.w;
            float u4 = v[4] + bv2.x, u5 = v[5] + bv2.y;
            float u6 = v[6] + bv2.z, u7 = v[7] + bv2.w;
            *(float4*)(yrow + n1) = make_float4(
                u0 >= 0.f ? u0 : a * u0, u1 >= 0.f ? u1 : a * u1,
                u2 >= 0.f ? u2 : a * u2, u3 >= 0.f ? u3 : a * u3);
            *(float4*)(yrow + n2) = make_float4(
                u4 >= 0.f ? u4 : a * u4, u5 >= 0.f ? u5 : a * u5,
                u6 >= 0.f ? u6 : a * u6, u7 >= 0.f ? u7 : a * u7);
        }
    }
}

// ---------------------------------------------------------------------------
// Head GEMM: P = y @ [W_mu | W_std]   (M=40960, N=64, K=512)
// ---------------------------------------------------------------------------
__global__ __launch_bounds__(256) void k_mustd() {
    __shared__ __align__(16) float As[2][32][128];
    __shared__ __align__(16) float Bs[2][32][64];
    const int tid = threadIdx.x, ty = tid >> 4, tx = tid & 15;
    const int bm = blockIdx.y * 128;
    ull acc[4][4] = {};
    auto loadA = [&](int k0, int idx) -> float4 {
        int row = idx >> 3, kq = (idx & 7) * 4;
        return *(const float4*)(g_y + (size_t)(bm + row) * Hdim + k0 + kq);
    };
    run_gemm1(acc, loadA, g_Bcomb, 64, 0, Hdim, As, Bs, tid);
    const int n = tx * 4;
#pragma unroll
    for (int p = 0; p < 4; p++) {
        float lo[4], hi[4];
#pragma unroll
        for (int c = 0; c < 4; c++) f32x2_unpack(acc[p][c], lo[c], hi[c]);
        int m0 = bm + ty * 8 + 2 * p;
        *(float4*)(g_p + (size_t)m0 * 64 + n) = make_float4(lo[0], lo[1], lo[2], lo[3]);
        *(float4*)(g_p + (size_t)(m0 + 1) * 64 + n) = make_float4(hi[0], hi[1], hi[2], hi[3]);
    }
}

// ---------------------------------------------------------------------------
// Tail: reparameterized sample, tanh, log_prob means. One block per b.
// ---------------------------------------------------------------------------
__global__ __launch_bounds__(256) void k_tail(const float* __restrict__ bmu,
                                              const float* __restrict__ bstd,
                                              const float* __restrict__ eps,
                                              float* __restrict__ out) {
    constexpr float STD_MIN = 2.0611536e-09f;
    constexpr float STD_MAX = 7.389056f;
    constexpr float HALF_LOG2PI = 0.9189385332046727f;
    const int b = blockIdx.x;
    const int tid = threadIdx.x;
    __shared__ float red[256];
    float lpsum = 0.0f;
    for (int idx = tid; idx < Ldim * Cdim; idx += 256) {
        int l = idx >> 5;
        int c = idx & 31;
        int row = b * Ldim + l;
        float mu = g_p[(size_t)row * 64 + c] + bmu[c];
        float sr = g_p[(size_t)row * 64 + 32 + c] + bstd[c];
        float sp = fmaxf(sr, 0.0f) + log1pf(expf(-fabsf(sr)));
        float sd = fminf(fmaxf(sp, STD_MIN), STD_MAX);
        float e  = eps[(size_t)row * Cdim + c];
        float comm = mu + e * sd;
        float co = tanhf(comm);
        out[(size_t)row * Cdim + c] = co;
        lpsum += -0.5f * e * e - logf(sd) - HALF_LOG2PI
                 - logf(1.0f - co * co + 1e-6f);
    }
    red[tid] = lpsum;
    __syncthreads();
    for (int s = 128; s > 0; s >>= 1) {
        if (tid < s) red[tid] += red[tid + s];
        __syncthreads();
    }
    if (tid == 0)
        out[OUT_CO + b] = red[0] * (1.0f / (Ldim * Cdim));
}

// ---------------------------------------------------------------------------
// Launch
// ---------------------------------------------------------------------------
extern "C" void kernel_launch(void* const* d_in, const int* in_sizes, int n_in,
                              void* d_out, int out_size) {
    const float* x    = (const float*)d_in[0];
    const float* Wr   = (const float*)d_in[1];
    const float* br   = (const float*)d_in[2];
    const float* Wz   = (const float*)d_in[3];
    const float* bz   = (const float*)d_in[4];
    const float* Wn   = (const float*)d_in[5];
    const float* bnn  = (const float*)d_in[6];
    const float* w1   = (const float*)d_in[7];
    const float* cb1  = (const float*)d_in[8];
    const float* w3   = (const float*)d_in[9];
    const float* cb3  = (const float*)d_in[10];
    const float* w5   = (const float*)d_in[11];
    const float* cb5  = (const float*)d_in[12];
    const float* w7   = (const float*)d_in[13];
    const float* cb7  = (const float*)d_in[14];
    const float* pa   = (const float*)d_in[15];
    const float* Wmu  = (const float*)d_in[16];
    const float* bmu  = (const float*)d_in[17];
    const float* Wstd = (const float*)d_in[18];
    const float* bstd = (const float*)d_in[19];
    const float* eps  = (const float*)d_in[20];
    float* out = (float*)d_out;

    k_pack<<<256, 256>>>(w1, w3, w5, w7, Wmu, Wstd, Wr, Wz);
    k_pre<<<dim3(24, 16), 256>>>(x, Wr, br, Wz, bz, Wn, bnn);
    k_step0<<<512, 256>>>();
    for (int t = 1; t < Ldim; t++) {
        k_rzA<<<dim3(8, 16, 2), 256>>>(t - 1);
        k_rzB<<<1024, 256>>>(t - 1);
        k_nA <<<dim3(4, 16, 4), 256>>>(Wn);
        k_nB <<<1024, 256>>>(t);
    }
    k_conv<<<dim3(1, 320, 4), 256>>>(cb1, cb3, cb5, cb7, pa);
    k_mustd<<<dim3(1, 320), 256>>>();
    k_tail<<<Bdim, 256>>>(bmu, bstd, eps, out);
}